// round 11
// baseline (speedup 1.0000x reference)
#include <cuda_runtime.h>
#include <cuda_fp16.h>
#include <cstdint>

// GRU: B=128, T=4096, I=6, H=32, O=2. One CTA per sequence, 4 warps:
//   warp 0: recurrence via tensor-core GEMV y(96) = W_hh(96x32).h(32):
//           12x mma.sync.m16n8k16 (f16 in, f32 accum), K-halves INDEPENDENT
//           (no D-chaining), gate inputs folded into MMA C operands.
//   warp 1: FC output, one chunk behind (exact f32 h ring)
//   warps 2,3: gx producers, one chunk ahead (f32)
// Layout: B fragments identical in all lanes -> all 8 D columns equal y.
// Lane owns unit u = gid + 8*(tig&1) + 16*((tig&2)>>1); r/z/n extracted from
// own c0/c2 via SELs (no shuffles). r/z C-slots pre-seeded with gx.x/gx.y.

#define Bq 128
#define Tq 4096
#define Iq 6
#define Hq 32
#define Oq 2
#define CH 32
#define NCH (Tq / CH)
#define HPAD 36   // f32 h ring rows: 144B

__device__ __forceinline__ float tanhm(float x) { float y; asm("tanh.approx.f32 %0, %1;" : "=f"(y) : "f"(x)); return y; }

__device__ __forceinline__ uint32_t saddr(const void* p) {
    uint32_t a;
    asm("{ .reg .u64 t; cvta.to.shared.u64 t, %1; cvt.u32.u64 %0, t; }" : "=r"(a) : "l"(p));
    return a;
}
__device__ __forceinline__ uint32_t ldv32(uint32_t a) {
    uint32_t v; asm volatile("ld.volatile.shared.b32 %0, [%1];" : "=r"(v) : "r"(a)); return v;
}
__device__ __forceinline__ void stv16(uint32_t a, unsigned short v) {
    asm volatile("st.volatile.shared.u16 [%0], %1;" :: "r"(a), "h"(v));
}
__device__ __forceinline__ void sts32p(uint32_t a, float v) {
    asm volatile("st.shared.f32 [%0], %1;" :: "r"(a), "f"(v));
}
__device__ __forceinline__ uint32_t packh2(float lo, float hi) {
    __half2 h = __floats2half2_rn(lo, hi);
    return *(uint32_t*)&h;
}

// D (fresh) = A*B + Cq
#define MMA_LD(D, A, B0, B1, C0, C1, C2, C3)                                   \
    asm volatile(                                                              \
        "mma.sync.aligned.m16n8k16.row.col.f32.f16.f16.f32 "                   \
        "{%0,%1,%2,%3}, {%4,%5,%6,%7}, {%8,%9}, {%10,%11,%12,%13};"            \
        : "=f"((D)[0]), "=f"((D)[1]), "=f"((D)[2]), "=f"((D)[3])               \
        : "r"((A)[0]), "r"((A)[1]), "r"((A)[2]), "r"((A)[3]),                  \
          "r"(B0), "r"(B1),                                                    \
          "f"(C0), "f"(C1), "f"(C2), "f"(C3))

__global__ void __launch_bounds__(128, 1) gru_seq_kernel(
    const float* __restrict__ x,        // [B, T, I]
    const int*   __restrict__ lengths,  // [B]
    const float* __restrict__ w_ih,     // [3H, I]
    const float* __restrict__ w_hh,     // [3H, H]  (96 x 32 row-major)
    const float* __restrict__ b_ih,     // [3H]
    const float* __restrict__ b_hh,     // [3H]
    const float* __restrict__ fc_w,     // [O, H]
    const float* __restrict__ fc_b,     // [O]
    float* __restrict__ out)            // [B, T, O]
{
    __shared__ __align__(16) float4 s_gx[2][CH][Hq];   // {pr, pz, pn, 0} by hidden unit
    __shared__ __align__(16) float  s_h[2][CH][HPAD];  // f32 h ring (for FC)
    __shared__ __align__(16) __half s_h16[2][CH][Hq];  // f16 h ring (64B rows)

    const int lane = threadIdx.x & 31;
    const int warp = threadIdx.x >> 5;
    const int b = blockIdx.x;
    const int L = lengths[b];

    const uint32_t hbase   = saddr(&s_h[0][0][0]);
    const uint32_t h16base = saddr(&s_h16[0][0][0]);

    if (warp == 0) {
        // ================= recurrence (tensor-core GEMV) =================
        const int gid = lane >> 2;          // groupID (0..7)
        const int tig = lane & 3;           // thread-in-group
        const int u = gid + ((tig & 1) << 3) + ((tig & 2) << 3);  // owned hidden unit
        const bool p0 = (tig == 0), p1 = (tig == 1), p2 = (tig == 2), p3 = (tig == 3);

        // A fragments: af[mt][kt][4]; m0,m1 = r rows; m2,m3 = z; m4,m5 = n.
        uint32_t af[6][2][4];
#pragma unroll
        for (int mt = 0; mt < 6; mt++)
#pragma unroll
            for (int kt = 0; kt < 2; kt++) {
                const int r0 = mt * 16 + gid;
                const int r1 = r0 + 8;
                const int c0 = kt * 16 + 2 * tig;
                af[mt][kt][0] = packh2(0.5f * w_hh[r0 * Hq + c0],     0.5f * w_hh[r0 * Hq + c0 + 1]);
                af[mt][kt][1] = packh2(0.5f * w_hh[r1 * Hq + c0],     0.5f * w_hh[r1 * Hq + c0 + 1]);
                af[mt][kt][2] = packh2(0.5f * w_hh[r0 * Hq + c0 + 8], 0.5f * w_hh[r0 * Hq + c0 + 9]);
                af[mt][kt][3] = packh2(0.5f * w_hh[r1 * Hq + c0 + 8], 0.5f * w_hh[r1 * Hq + c0 + 9]);
            }
        // n-tile bias C-quads (0.5*bhn by row)
        const float bn4a = 0.5f * b_hh[2 * Hq + gid];
        const float bn4b = 0.5f * b_hh[2 * Hq + gid + 8];
        const float bn5a = 0.5f * b_hh[2 * Hq + 16 + gid];
        const float bn5b = 0.5f * b_hh[2 * Hq + 24 + gid];
        const float fz = 0.0f;

        stv16(h16base + ((1 * CH + (CH - 1)) * Hq + u) * 2, (unsigned short)0);  // h_{-1}=0
        float hk = 0.f;
        uint32_t hprev16 = h16base + ((1 * CH + (CH - 1)) * Hq) * 2;
        const uint32_t tig4 = tig * 4;

#define GRU_STEP(CBUF, S, H16ROW, HROWF)                                       \
        {                                                                      \
            float4 gx = s_gx[CBUF][S][u];                                      \
            /* off-chain: gate-input C slots (own c0/c2 only is read) */       \
            float crA0 = p0 ? gx.x : 0.f, crA2 = p1 ? gx.x : 0.f;              \
            float crB0 = p2 ? gx.x : 0.f, crB2 = p3 ? gx.x : 0.f;              \
            float czA0 = p0 ? gx.y : 0.f, czA2 = p1 ? gx.y : 0.f;              \
            float czB0 = p2 ? gx.y : 0.f, czB2 = p3 ? gx.y : 0.f;              \
            uint32_t b0 = ldv32(hprev16 + tig4);                               \
            uint32_t b1 = ldv32(hprev16 + 16 + tig4);                          \
            uint32_t b2 = ldv32(hprev16 + 32 + tig4);                          \
            uint32_t b3 = ldv32(hprev16 + 48 + tig4);                          \
            float dR0a[4], dR0b[4], dR1a[4], dR1b[4];                          \
            float dZ0a[4], dZ0b[4], dZ1a[4], dZ1b[4];                          \
            float dN0a[4], dN0b[4], dN1a[4], dN1b[4];                          \
            /* r first (critical), k-halves independent */                     \
            MMA_LD(dR0a, af[0][0], b0, b1, crA0, fz, crA2, fz);                \
            MMA_LD(dR0b, af[0][1], b2, b3, fz, fz, fz, fz);                    \
            MMA_LD(dR1a, af[1][0], b0, b1, crB0, fz, crB2, fz);                \
            MMA_LD(dR1b, af[1][1], b2, b3, fz, fz, fz, fz);                    \
            /* n second (needed after tanh(tr)) */                             \
            MMA_LD(dN0a, af[4][0], b0, b1, bn4a, fz, bn4b, fz);                \
            MMA_LD(dN0b, af[4][1], b2, b3, fz, fz, fz, fz);                    \
            MMA_LD(dN1a, af[5][0], b0, b1, bn5a, fz, bn5b, fz);                \
            MMA_LD(dN1b, af[5][1], b2, b3, fz, fz, fz, fz);                    \
            /* z last (needed at the very end) */                              \
            MMA_LD(dZ0a, af[2][0], b0, b1, czA0, fz, czA2, fz);                \
            MMA_LD(dZ0b, af[2][1], b2, b3, fz, fz, fz, fz);                    \
            MMA_LD(dZ1a, af[3][0], b0, b1, czB0, fz, czB2, fz);                \
            MMA_LD(dZ1b, af[3][1], b2, b3, fz, fz, fz, fz);                    \
            float rA = p0 ? dR0a[0] : p1 ? dR0a[2] : p2 ? dR1a[0] : dR1a[2];   \
            float rB = p0 ? dR0b[0] : p1 ? dR0b[2] : p2 ? dR1b[0] : dR1b[2];   \
            float tr = tanhm(rA + rB);             /* arg already has gx.x */  \
            float nA = p0 ? dN0a[0] : p1 ? dN0a[2] : p2 ? dN1a[0] : dN1a[2];   \
            float nB = p0 ? dN0b[0] : p1 ? dN0b[2] : p2 ? dN1b[0] : dN1b[2];   \
            float ns = nA + nB;                    /* 0.5*(Wn.h + bhn) */      \
            float nsc = gx.z + ns;                                             \
            float zA = p0 ? dZ0a[0] : p1 ? dZ0a[2] : p2 ? dZ1a[0] : dZ1a[2];   \
            float zB = p0 ? dZ0b[0] : p1 ? dZ0b[2] : p2 ? dZ1b[0] : dZ1b[2];   \
            float tz = tanhm(zA + zB);                                         \
            float argn = fmaf(tr, ns, nsc);        /* xn + r*hn */             \
            float tn = tanhm(argn);                                            \
            float zz = fmaf(0.5f, tz, 0.5f);                                   \
            float cb = zz * hk;                                                \
            float ca = 1.0f - zz;                                              \
            hk = fmaf(ca, tn, cb);                 /* h_new (f32) */           \
            stv16((H16ROW) + u * 2, __half_as_ushort(__float2half_rn(hk)));    \
            sts32p((HROWF) + u * 4, hk);           /* exact copy for FC */     \
            hprev16 = (H16ROW);                                                \
        }

        for (int c = 0; c < NCH; c++) {
            __syncthreads();
            int nst = L - c * CH;
            nst = nst < 0 ? 0 : (nst > CH ? CH : nst);
            const int cb1 = c & 1;
            uint32_t h16row = h16base + (cb1 * CH * Hq) * 2;
            uint32_t hrowf = hbase + (cb1 * CH * HPAD) * 4;
            if (nst == CH) {
#pragma unroll 4
                for (int s = 0; s < CH; s++) {
                    GRU_STEP(cb1, s, h16row, hrowf)
                    h16row += Hq * 2;
                    hrowf += HPAD * 4;
                }
            } else {
#pragma unroll 1
                for (int s = 0; s < nst; s++) {
                    GRU_STEP(cb1, s, h16row, hrowf)
                    h16row += Hq * 2;
                    hrowf += HPAD * 4;
                }
            }
        }
        __syncthreads();
#undef GRU_STEP
    } else if (warp == 1) {
        // ================= FC output, one chunk behind =================
        for (int c = 0; c < NCH; c++) {
            __syncthreads();
            if (c > 0) {
                const int cp = c - 1;
                const int t = cp * CH + lane;
                float o0 = __ldg(fc_b + 0);
                float o1 = __ldg(fc_b + 1);
                if (t < L) {
                    const float* hr = &s_h[cp & 1][lane][0];
#pragma unroll
                    for (int j = 0; j < Hq; j++) {
                        float hv = hr[j];
                        o0 = fmaf(__ldg(fc_w + j), hv, o0);
                        o1 = fmaf(__ldg(fc_w + Hq + j), hv, o1);
                    }
                }
                float2 v = make_float2(o0, o1);
                *reinterpret_cast<float2*>(out + ((size_t)b * Tq + t) * Oq) = v;
            }
        }
        __syncthreads();
        {   // epilogue: last chunk
            const int cp = NCH - 1;
            const int t = cp * CH + lane;
            float o0 = __ldg(fc_b + 0);
            float o1 = __ldg(fc_b + 1);
            if (t < L) {
                const float* hr = &s_h[cp & 1][lane][0];
#pragma unroll
                for (int j = 0; j < Hq; j++) {
                    float hv = hr[j];
                    o0 = fmaf(__ldg(fc_w + j), hv, o0);
                    o1 = fmaf(__ldg(fc_w + Hq + j), hv, o1);
                }
            }
            float2 v = make_float2(o0, o1);
            *reinterpret_cast<float2*>(out + ((size_t)b * Tq + t) * Oq) = v;
        }
    } else {
        // ================= producers (warps 2,3), one chunk ahead =================
        float wiA[Iq], wiB[Iq], wiC[Iq];
#pragma unroll
        for (int i = 0; i < Iq; i++) {
            wiA[i] = 0.5f * w_ih[lane * Iq + i];          // pre-scaled for tanh-form
            wiB[i] = 0.5f * w_ih[(Hq + lane) * Iq + i];
            wiC[i] = w_ih[(2 * Hq + lane) * Iq + i];      // pn: unscaled
        }
        const float biA = 0.5f * (b_ih[lane] + b_hh[lane]);
        const float biB = 0.5f * (b_ih[Hq + lane] + b_hh[Hq + lane]);
        const float biC = b_ih[2 * Hq + lane];
        const int s0 = (warp == 3) ? (CH / 2) : 0;

        // prologue: chunk 0
        {
            const float* xp = x + ((size_t)b * Tq + s0) * Iq;
#pragma unroll 1
            for (int s = 0; s < CH / 2; s++) {
                float xv[Iq];
#pragma unroll
                for (int i = 0; i < Iq; i++) xv[i] = xp[i];
                float gr = biA, gz = biB, gn = biC;
#pragma unroll
                for (int i = 0; i < Iq; i++) {
                    gr = fmaf(wiA[i], xv[i], gr);
                    gz = fmaf(wiB[i], xv[i], gz);
                    gn = fmaf(wiC[i], xv[i], gn);
                }
                s_gx[0][s0 + s][lane] = make_float4(gr, gz, gn, 0.0f);
                xp += Iq;
            }
        }
        for (int c = 0; c < NCH; c++) {
            __syncthreads();
            const int cc = c + 1;
            if (cc < NCH) {
                const float* xp = x + ((size_t)b * Tq + cc * CH + s0) * Iq;
#pragma unroll 1
                for (int s = 0; s < CH / 2; s++) {
                    float xv[Iq];
#pragma unroll
                    for (int i = 0; i < Iq; i++) xv[i] = xp[i];
                    float gr = biA, gz = biB, gn = biC;
#pragma unroll
                    for (int i = 0; i < Iq; i++) {
                        gr = fmaf(wiA[i], xv[i], gr);
                        gz = fmaf(wiB[i], xv[i], gz);
                        gn = fmaf(wiC[i], xv[i], gn);
                    }
                    s_gx[cc & 1][s0 + s][lane] = make_float4(gr, gz, gn, 0.0f);
                    xp += Iq;
                }
            }
        }
        __syncthreads();
    }
}

extern "C" void kernel_launch(void* const* d_in, const int* in_sizes, int n_in,
                              void* d_out, int out_size) {
    const float* x       = (const float*)d_in[0];
    const int*   lengths = (const int*)d_in[1];
    const float* w_ih    = (const float*)d_in[2];
    const float* w_hh    = (const float*)d_in[3];
    const float* b_ih    = (const float*)d_in[4];
    const float* b_hh    = (const float*)d_in[5];
    const float* fc_w    = (const float*)d_in[6];
    const float* fc_b    = (const float*)d_in[7];
    float* out = (float*)d_out;

    gru_seq_kernel<<<Bq, 128>>>(x, lengths, w_ih, w_hh, b_ih, b_hh, fc_w, fc_b, out);
}

// round 12
// speedup vs baseline: 1.0970x; 1.0970x over previous
#include <cuda_runtime.h>
#include <cuda_fp16.h>
#include <cstdint>

// GRU: B=128, T=4096, I=6, H=32, O=2. One CTA per sequence, 4 warps.
// HYBRID recurrence (warp 0): r,z gates on the FMA pipe (HFMA2, f16x2 dots),
// n gate on the tensor pipe (4x mma.m16n8k16, f32 accum) — the two pipes run
// concurrently on the SMSP, and n's MMA latency hides under r/z issue+tanh.
// Evidence: R9 (all-HFMA2)=220cyc, R10 (all-HMMA)=212cyc, R11(+ALU)=268cyc
// => HMMA rt~16 (tensor-throughput-bound); splitting across pipes overlaps.
// Unit ownership follows the MMA D-fragment: u = gid + 8*(tig&1) + 16*(tig>>1).
// warp 1: FC output, one chunk behind (exact f32 h ring)
// warps 2,3: gx producers, one chunk ahead (f32)

#define Bq 128
#define Tq 4096
#define Iq 6
#define Hq 32
#define Oq 2
#define CH 32
#define NCH (Tq / CH)
#define HPAD 36   // f32 h ring rows: 144B

__device__ __forceinline__ float tanhm(float x) { float y; asm("tanh.approx.f32 %0, %1;" : "=f"(y) : "f"(x)); return y; }

__device__ __forceinline__ uint32_t saddr(const void* p) {
    uint32_t a;
    asm("{ .reg .u64 t; cvta.to.shared.u64 t, %1; cvt.u32.u64 %0, t; }" : "=r"(a) : "l"(p));
    return a;
}
__device__ __forceinline__ uint32_t ldv32(uint32_t a) {
    uint32_t v; asm volatile("ld.volatile.shared.b32 %0, [%1];" : "=r"(v) : "r"(a)); return v;
}
__device__ __forceinline__ void ldsv128u(uint32_t a, uint32_t& x, uint32_t& y, uint32_t& z, uint32_t& w) {
    asm volatile("ld.volatile.shared.v4.b32 {%0, %1, %2, %3}, [%4];" : "=r"(x), "=r"(y), "=r"(z), "=r"(w) : "r"(a));
}
__device__ __forceinline__ void stv16(uint32_t a, unsigned short v) {
    asm volatile("st.volatile.shared.u16 [%0], %1;" :: "r"(a), "h"(v));
}
__device__ __forceinline__ void sts32p(uint32_t a, float v) {
    asm volatile("st.shared.f32 [%0], %1;" :: "r"(a), "f"(v));
}
__device__ __forceinline__ uint32_t packh2(float lo, float hi) {
    __half2 h = __floats2half2_rn(lo, hi);
    return *(uint32_t*)&h;
}
__device__ __forceinline__ __half2 u2h2(uint32_t u) { __half2 h; *(uint32_t*)&h = u; return h; }

// D (fresh) = A*B + Cq
#define MMA_LD(D, A, B0, B1, C0, C1, C2, C3)                                   \
    asm volatile(                                                              \
        "mma.sync.aligned.m16n8k16.row.col.f32.f16.f16.f32 "                   \
        "{%0,%1,%2,%3}, {%4,%5,%6,%7}, {%8,%9}, {%10,%11,%12,%13};"            \
        : "=f"((D)[0]), "=f"((D)[1]), "=f"((D)[2]), "=f"((D)[3])               \
        : "r"((A)[0]), "r"((A)[1]), "r"((A)[2]), "r"((A)[3]),                  \
          "r"(B0), "r"(B1),                                                    \
          "f"(C0), "f"(C1), "f"(C2), "f"(C3))

// D += A*B (in place)
#define MMA_ACC(D, A, B0, B1)                                                  \
    asm volatile(                                                              \
        "mma.sync.aligned.m16n8k16.row.col.f32.f16.f16.f32 "                   \
        "{%0,%1,%2,%3}, {%4,%5,%6,%7}, {%8,%9}, {%0,%1,%2,%3};"                \
        : "+f"((D)[0]), "+f"((D)[1]), "+f"((D)[2]), "+f"((D)[3])               \
        : "r"((A)[0]), "r"((A)[1]), "r"((A)[2]), "r"((A)[3]),                  \
          "r"(B0), "r"(B1))

__global__ void __launch_bounds__(128, 1) gru_seq_kernel(
    const float* __restrict__ x,        // [B, T, I]
    const int*   __restrict__ lengths,  // [B]
    const float* __restrict__ w_ih,     // [3H, I]
    const float* __restrict__ w_hh,     // [3H, H]  (96 x 32 row-major)
    const float* __restrict__ b_ih,     // [3H]
    const float* __restrict__ b_hh,     // [3H]
    const float* __restrict__ fc_w,     // [O, H]
    const float* __restrict__ fc_b,     // [O]
    float* __restrict__ out)            // [B, T, O]
{
    __shared__ __align__(16) float4 s_gx[2][CH][Hq];   // {pr, pz, pn, 0} by hidden unit
    __shared__ __align__(16) float  s_h[2][CH][HPAD];  // f32 h ring (for FC)
    __shared__ __align__(16) __half s_h16[2][CH][Hq];  // f16 h ring (64B rows)

    const int lane = threadIdx.x & 31;
    const int warp = threadIdx.x >> 5;
    const int b = blockIdx.x;
    const int L = lengths[b];

    const uint32_t hbase   = saddr(&s_h[0][0][0]);
    const uint32_t h16base = saddr(&s_h16[0][0][0]);

    if (warp == 0) {
        // ================= recurrence (hybrid fma + tensor) =================
        const int gid = lane >> 2;          // groupID (0..7)
        const int tig = lane & 3;           // thread-in-group
        const int u = gid + ((tig & 1) << 3) + ((tig & 2) << 3);  // owned hidden unit
        const bool p1 = (tig == 1), p3 = (tig == 3);
        const bool pt2 = (tig & 2) != 0;

        // r,z recurrent weights for unit u (HFMA2 path), pre-scaled by 0.5
        __half2 wr[16], wz[16];
        {
            const float* rrw = w_hh + u * Hq;
            const float* rzw = w_hh + (Hq + u) * Hq;
#pragma unroll
            for (int j = 0; j < 16; j++) {
                wr[j] = __floats2half2_rn(0.5f * rrw[2 * j], 0.5f * rrw[2 * j + 1]);
                wz[j] = __floats2half2_rn(0.5f * rzw[2 * j], 0.5f * rzw[2 * j + 1]);
            }
        }
        // n-gate A fragments (2 m-tiles x 2 k-halves), rows at 2H offset, 0.5-scaled
        uint32_t af[2][2][4];
#pragma unroll
        for (int mt = 0; mt < 2; mt++)
#pragma unroll
            for (int kt = 0; kt < 2; kt++) {
                const int r0 = 2 * Hq + mt * 16 + gid;
                const int r1 = r0 + 8;
                const int c0 = kt * 16 + 2 * tig;
                af[mt][kt][0] = packh2(0.5f * w_hh[r0 * Hq + c0],     0.5f * w_hh[r0 * Hq + c0 + 1]);
                af[mt][kt][1] = packh2(0.5f * w_hh[r1 * Hq + c0],     0.5f * w_hh[r1 * Hq + c0 + 1]);
                af[mt][kt][2] = packh2(0.5f * w_hh[r0 * Hq + c0 + 8], 0.5f * w_hh[r0 * Hq + c0 + 9]);
                af[mt][kt][3] = packh2(0.5f * w_hh[r1 * Hq + c0 + 8], 0.5f * w_hh[r1 * Hq + c0 + 9]);
            }
        // n-tile bias C-quads (0.5*bhn by row)
        const float bn0a = 0.5f * b_hh[2 * Hq + gid];
        const float bn0b = 0.5f * b_hh[2 * Hq + gid + 8];
        const float bn1a = 0.5f * b_hh[2 * Hq + 16 + gid];
        const float bn1b = 0.5f * b_hh[2 * Hq + 24 + gid];
        const float fz = 0.0f;

        stv16(h16base + ((1 * CH + (CH - 1)) * Hq + u) * 2, (unsigned short)0);  // h_{-1}=0
        float hk = 0.f;
        uint32_t hprev16 = h16base + ((1 * CH + (CH - 1)) * Hq) * 2;
        const uint32_t tig4 = tig * 4;

#define GRU_STEP(CBUF, S, H16ROW, HROWF)                                       \
        {                                                                      \
            float4 gx = s_gx[CBUF][S][u];                                      \
            /* MMA B fragments (tig-sliced) — issue first: tensor latency */   \
            uint32_t b0 = ldv32(hprev16 + tig4);                               \
            uint32_t b1 = ldv32(hprev16 + 16 + tig4);                          \
            uint32_t b2 = ldv32(hprev16 + 32 + tig4);                          \
            uint32_t b3 = ldv32(hprev16 + 48 + tig4);                          \
            float dN0[4], dN1[4];                                              \
            MMA_LD(dN0, af[0][0], b0, b1, bn0a, fz, bn0b, fz);                 \
            MMA_ACC(dN0, af[0][1], b2, b3);                                    \
            MMA_LD(dN1, af[1][0], b0, b1, bn1a, fz, bn1b, fz);                 \
            MMA_ACC(dN1, af[1][1], b2, b3);                                    \
            /* full h row (broadcast) for the fma-pipe r,z dots */             \
            uint32_t hu[16];                                                   \
            ldsv128u(hprev16 +  0, hu[0],  hu[1],  hu[2],  hu[3]);             \
            ldsv128u(hprev16 + 16, hu[4],  hu[5],  hu[6],  hu[7]);             \
            ldsv128u(hprev16 + 32, hu[8],  hu[9],  hu[10], hu[11]);            \
            ldsv128u(hprev16 + 48, hu[12], hu[13], hu[14], hu[15]);            \
            __half2 h2[16];                                                    \
            _Pragma("unroll")                                                  \
            for (int j = 0; j < 16; j++) h2[j] = u2h2(hu[j]);                  \
            const __half2 hz2 = __half2half2(__ushort_as_half((unsigned short)0)); \
            /* r-dot: 4 accumulators (critical path) */                        \
            __half2 ar0 = hz2, ar1 = hz2, ar2 = hz2, ar3 = hz2;                \
            _Pragma("unroll")                                                  \
            for (int j = 0; j < 16; j += 4) {                                  \
                ar0 = __hfma2(wr[j],     h2[j],     ar0);                      \
                ar1 = __hfma2(wr[j + 1], h2[j + 1], ar1);                      \
                ar2 = __hfma2(wr[j + 2], h2[j + 2], ar2);                      \
                ar3 = __hfma2(wr[j + 3], h2[j + 3], ar3);                      \
            }                                                                  \
            __half2 sr = __hadd2(__hadd2(ar0, ar1), __hadd2(ar2, ar3));        \
            /* z-dot: 2 accumulators (slack path) */                           \
            __half2 az0 = hz2, az1 = hz2;                                      \
            _Pragma("unroll")                                                  \
            for (int j = 0; j < 16; j += 2) {                                  \
                az0 = __hfma2(wz[j],     h2[j],     az0);                      \
                az1 = __hfma2(wz[j + 1], h2[j + 1], az1);                      \
            }                                                                  \
            __half2 sz = __hadd2(az0, az1);                                    \
            /* packed cross-half reduce for r,z together */                    \
            __half2 pa = __lows2half2(sr, sz);                                 \
            __half2 pb = __highs2half2(sr, sz);                                \
            __half2 srz = __hadd2(pa, pb);          /* {rdot, zdot} */         \
            float2 frz = __half22float2(srz);                                  \
            float tr = tanhm(frz.x + gx.x);                                    \
            float tz = tanhm(frz.y + gx.y);                                    \
            /* n extraction: depth-2 select tree over MMA quads */             \
            float nsA = p1 ? dN0[2] : dN0[0];                                  \
            float nsB = p3 ? dN1[2] : dN1[0];                                  \
            float ns = pt2 ? nsB : nsA;             /* 0.5*(Wn.h + bhn) */     \
            float nsc = gx.z + ns;                                             \
            float argn = fmaf(tr, ns, nsc);         /* xn + r*hn */            \
            float tn = tanhm(argn);                                            \
            float zz = fmaf(0.5f, tz, 0.5f);                                   \
            float cb = zz * hk;                                                \
            float ca = 1.0f - zz;                                              \
            hk = fmaf(ca, tn, cb);                  /* h_new (f32) */          \
            stv16((H16ROW) + u * 2, __half_as_ushort(__float2half_rn(hk)));    \
            sts32p((HROWF) + u * 4, hk);            /* exact copy for FC */    \
            hprev16 = (H16ROW);                                                \
        }

        for (int c = 0; c < NCH; c++) {
            __syncthreads();
            int nst = L - c * CH;
            nst = nst < 0 ? 0 : (nst > CH ? CH : nst);
            const int cb1 = c & 1;
            uint32_t h16row = h16base + (cb1 * CH * Hq) * 2;
            uint32_t hrowf = hbase + (cb1 * CH * HPAD) * 4;
            if (nst == CH) {
#pragma unroll 4
                for (int s = 0; s < CH; s++) {
                    GRU_STEP(cb1, s, h16row, hrowf)
                    h16row += Hq * 2;
                    hrowf += HPAD * 4;
                }
            } else {
#pragma unroll 1
                for (int s = 0; s < nst; s++) {
                    GRU_STEP(cb1, s, h16row, hrowf)
                    h16row += Hq * 2;
                    hrowf += HPAD * 4;
                }
            }
        }
        __syncthreads();
#undef GRU_STEP
    } else if (warp == 1) {
        // ================= FC output, one chunk behind =================
        for (int c = 0; c < NCH; c++) {
            __syncthreads();
            if (c > 0) {
                const int cp = c - 1;
                const int t = cp * CH + lane;
                float o0 = __ldg(fc_b + 0);
                float o1 = __ldg(fc_b + 1);
                if (t < L) {
                    const float* hr = &s_h[cp & 1][lane][0];
#pragma unroll
                    for (int j = 0; j < Hq; j++) {
                        float hv = hr[j];
                        o0 = fmaf(__ldg(fc_w + j), hv, o0);
                        o1 = fmaf(__ldg(fc_w + Hq + j), hv, o1);
                    }
                }
                float2 v = make_float2(o0, o1);
                *reinterpret_cast<float2*>(out + ((size_t)b * Tq + t) * Oq) = v;
            }
        }
        __syncthreads();
        {   // epilogue: last chunk
            const int cp = NCH - 1;
            const int t = cp * CH + lane;
            float o0 = __ldg(fc_b + 0);
            float o1 = __ldg(fc_b + 1);
            if (t < L) {
                const float* hr = &s_h[cp & 1][lane][0];
#pragma unroll
                for (int j = 0; j < Hq; j++) {
                    float hv = hr[j];
                    o0 = fmaf(__ldg(fc_w + j), hv, o0);
                    o1 = fmaf(__ldg(fc_w + Hq + j), hv, o1);
                }
            }
            float2 v = make_float2(o0, o1);
            *reinterpret_cast<float2*>(out + ((size_t)b * Tq + t) * Oq) = v;
        }
    } else {
        // ================= producers (warps 2,3), one chunk ahead =================
        float wiA[Iq], wiB[Iq], wiC[Iq];
#pragma unroll
        for (int i = 0; i < Iq; i++) {
            wiA[i] = 0.5f * w_ih[lane * Iq + i];          // pre-scaled for tanh-form
            wiB[i] = 0.5f * w_ih[(Hq + lane) * Iq + i];
            wiC[i] = w_ih[(2 * Hq + lane) * Iq + i];      // pn: unscaled
        }
        const float biA = 0.5f * (b_ih[lane] + b_hh[lane]);
        const float biB = 0.5f * (b_ih[Hq + lane] + b_hh[Hq + lane]);
        const float biC = b_ih[2 * Hq + lane];
        const int s0 = (warp == 3) ? (CH / 2) : 0;

        // prologue: chunk 0
        {
            const float* xp = x + ((size_t)b * Tq + s0) * Iq;
#pragma unroll 1
            for (int s = 0; s < CH / 2; s++) {
                float xv[Iq];
#pragma unroll
                for (int i = 0; i < Iq; i++) xv[i] = xp[i];
                float gr = biA, gz = biB, gn = biC;
#pragma unroll
                for (int i = 0; i < Iq; i++) {
                    gr = fmaf(wiA[i], xv[i], gr);
                    gz = fmaf(wiB[i], xv[i], gz);
                    gn = fmaf(wiC[i], xv[i], gn);
                }
                s_gx[0][s0 + s][lane] = make_float4(gr, gz, gn, 0.0f);
                xp += Iq;
            }
        }
        for (int c = 0; c < NCH; c++) {
            __syncthreads();
            const int cc = c + 1;
            if (cc < NCH) {
                const float* xp = x + ((size_t)b * Tq + cc * CH + s0) * Iq;
#pragma unroll 1
                for (int s = 0; s < CH / 2; s++) {
                    float xv[Iq];
#pragma unroll
                    for (int i = 0; i < Iq; i++) xv[i] = xp[i];
                    float gr = biA, gz = biB, gn = biC;
#pragma unroll
                    for (int i = 0; i < Iq; i++) {
                        gr = fmaf(wiA[i], xv[i], gr);
                        gz = fmaf(wiB[i], xv[i], gz);
                        gn = fmaf(wiC[i], xv[i], gn);
                    }
                    s_gx[cc & 1][s0 + s][lane] = make_float4(gr, gz, gn, 0.0f);
                    xp += Iq;
                }
            }
        }
        __syncthreads();
    }
}

extern "C" void kernel_launch(void* const* d_in, const int* in_sizes, int n_in,
                              void* d_out, int out_size) {
    const float* x       = (const float*)d_in[0];
    const int*   lengths = (const int*)d_in[1];
    const float* w_ih    = (const float*)d_in[2];
    const float* w_hh    = (const float*)d_in[3];
    const float* b_ih    = (const float*)d_in[4];
    const float* b_hh    = (const float*)d_in[5];
    const float* fc_w    = (const float*)d_in[6];
    const float* fc_b    = (const float*)d_in[7];
    float* out = (float*)d_out;

    gru_seq_kernel<<<Bq, 128>>>(x, lengths, w_ih, w_hh, b_ih, b_hh, fc_w, fc_b, out);
}

// round 13
// speedup vs baseline: 1.1168x; 1.0181x over previous
#include <cuda_runtime.h>
#include <cuda_fp16.h>
#include <cstdint>

// GRU: B=128, T=4096, I=6, H=32, O=2. One CTA per sequence, 4 warps.
// HYBRID recurrence (warp 0): r,z gates on FMA pipe (HFMA2 dots), n gate on
// tensor pipe via 4 INDEPENDENT mma.m16n8k16 (k-halves unchained; merged by
// scalar add after per-lane selection). Fixes R12's serial MMA_LD->MMA_ACC
// n-chain (~120cyc) down to one MMA latency (~60cyc).
// Unit ownership follows the MMA D-fragment: u = gid + 8*(tig&1) + 16*(tig>>1).
// warp 1: FC output, one chunk behind (exact f32 h ring)
// warps 2,3: gx producers, one chunk ahead (f32)

#define Bq 128
#define Tq 4096
#define Iq 6
#define Hq 32
#define Oq 2
#define CH 32
#define NCH (Tq / CH)
#define HPAD 36   // f32 h ring rows: 144B

__device__ __forceinline__ float tanhm(float x) { float y; asm("tanh.approx.f32 %0, %1;" : "=f"(y) : "f"(x)); return y; }

__device__ __forceinline__ uint32_t saddr(const void* p) {
    uint32_t a;
    asm("{ .reg .u64 t; cvta.to.shared.u64 t, %1; cvt.u32.u64 %0, t; }" : "=r"(a) : "l"(p));
    return a;
}
__device__ __forceinline__ uint32_t ldv32(uint32_t a) {
    uint32_t v; asm volatile("ld.volatile.shared.b32 %0, [%1];" : "=r"(v) : "r"(a)); return v;
}
__device__ __forceinline__ void ldsv128u(uint32_t a, uint32_t& x, uint32_t& y, uint32_t& z, uint32_t& w) {
    asm volatile("ld.volatile.shared.v4.b32 {%0, %1, %2, %3}, [%4];" : "=r"(x), "=r"(y), "=r"(z), "=r"(w) : "r"(a));
}
__device__ __forceinline__ void stv16(uint32_t a, unsigned short v) {
    asm volatile("st.volatile.shared.u16 [%0], %1;" :: "r"(a), "h"(v));
}
__device__ __forceinline__ void sts32p(uint32_t a, float v) {
    asm volatile("st.shared.f32 [%0], %1;" :: "r"(a), "f"(v));
}
__device__ __forceinline__ uint32_t packh2(float lo, float hi) {
    __half2 h = __floats2half2_rn(lo, hi);
    return *(uint32_t*)&h;
}
__device__ __forceinline__ __half2 u2h2(uint32_t u) { __half2 h; *(uint32_t*)&h = u; return h; }

// D (fresh) = A*B + Cq
#define MMA_LD(D, A, B0, B1, C0, C1, C2, C3)                                   \
    asm volatile(                                                              \
        "mma.sync.aligned.m16n8k16.row.col.f32.f16.f16.f32 "                   \
        "{%0,%1,%2,%3}, {%4,%5,%6,%7}, {%8,%9}, {%10,%11,%12,%13};"            \
        : "=f"((D)[0]), "=f"((D)[1]), "=f"((D)[2]), "=f"((D)[3])               \
        : "r"((A)[0]), "r"((A)[1]), "r"((A)[2]), "r"((A)[3]),                  \
          "r"(B0), "r"(B1),                                                    \
          "f"(C0), "f"(C1), "f"(C2), "f"(C3))

__global__ void __launch_bounds__(128, 1) gru_seq_kernel(
    const float* __restrict__ x,        // [B, T, I]
    const int*   __restrict__ lengths,  // [B]
    const float* __restrict__ w_ih,     // [3H, I]
    const float* __restrict__ w_hh,     // [3H, H]  (96 x 32 row-major)
    const float* __restrict__ b_ih,     // [3H]
    const float* __restrict__ b_hh,     // [3H]
    const float* __restrict__ fc_w,     // [O, H]
    const float* __restrict__ fc_b,     // [O]
    float* __restrict__ out)            // [B, T, O]
{
    __shared__ __align__(16) float4 s_gx[2][CH][Hq];   // {pr, pz, pn, 0} by hidden unit
    __shared__ __align__(16) float  s_h[2][CH][HPAD];  // f32 h ring (for FC)
    __shared__ __align__(16) __half s_h16[2][CH][Hq];  // f16 h ring (64B rows)

    const int lane = threadIdx.x & 31;
    const int warp = threadIdx.x >> 5;
    const int b = blockIdx.x;
    const int L = lengths[b];

    const uint32_t hbase   = saddr(&s_h[0][0][0]);
    const uint32_t h16base = saddr(&s_h16[0][0][0]);

    if (warp == 0) {
        // ================= recurrence (hybrid fma + tensor) =================
        const int gid = lane >> 2;          // groupID (0..7)
        const int tig = lane & 3;           // thread-in-group
        const int u = gid + ((tig & 1) << 3) + ((tig & 2) << 3);  // owned hidden unit
        const bool p1 = (tig == 1), p3 = (tig == 3);
        const bool pt2 = (tig & 2) != 0;

        // r,z recurrent weights for unit u (HFMA2 path), pre-scaled by 0.5
        __half2 wr[16], wz[16];
        {
            const float* rrw = w_hh + u * Hq;
            const float* rzw = w_hh + (Hq + u) * Hq;
#pragma unroll
            for (int j = 0; j < 16; j++) {
                wr[j] = __floats2half2_rn(0.5f * rrw[2 * j], 0.5f * rrw[2 * j + 1]);
                wz[j] = __floats2half2_rn(0.5f * rzw[2 * j], 0.5f * rzw[2 * j + 1]);
            }
        }
        // n-gate A fragments (2 m-tiles x 2 k-halves), rows at 2H offset, 0.5-scaled
        uint32_t af[2][2][4];
#pragma unroll
        for (int mt = 0; mt < 2; mt++)
#pragma unroll
            for (int kt = 0; kt < 2; kt++) {
                const int r0 = 2 * Hq + mt * 16 + gid;
                const int r1 = r0 + 8;
                const int c0 = kt * 16 + 2 * tig;
                af[mt][kt][0] = packh2(0.5f * w_hh[r0 * Hq + c0],     0.5f * w_hh[r0 * Hq + c0 + 1]);
                af[mt][kt][1] = packh2(0.5f * w_hh[r1 * Hq + c0],     0.5f * w_hh[r1 * Hq + c0 + 1]);
                af[mt][kt][2] = packh2(0.5f * w_hh[r0 * Hq + c0 + 8], 0.5f * w_hh[r0 * Hq + c0 + 9]);
                af[mt][kt][3] = packh2(0.5f * w_hh[r1 * Hq + c0 + 8], 0.5f * w_hh[r1 * Hq + c0 + 9]);
            }
        // n-tile bias C-quads (0.5*bhn by row) — only on k-half 0
        const float bn0a = 0.5f * b_hh[2 * Hq + gid];
        const float bn0b = 0.5f * b_hh[2 * Hq + gid + 8];
        const float bn1a = 0.5f * b_hh[2 * Hq + 16 + gid];
        const float bn1b = 0.5f * b_hh[2 * Hq + 24 + gid];
        const float fz = 0.0f;

        stv16(h16base + ((1 * CH + (CH - 1)) * Hq + u) * 2, (unsigned short)0);  // h_{-1}=0
        float hk = 0.f;
        uint32_t hprev16 = h16base + ((1 * CH + (CH - 1)) * Hq) * 2;
        const uint32_t tig4 = tig * 4;

#define GRU_STEP(CBUF, S, H16ROW, HROWF)                                       \
        {                                                                      \
            float4 gx = s_gx[CBUF][S][u];                                      \
            /* B fragments first: MMAs launch ASAP */                          \
            uint32_t b0 = ldv32(hprev16 + tig4);                               \
            uint32_t b1 = ldv32(hprev16 + 16 + tig4);                          \
            uint32_t b2 = ldv32(hprev16 + 32 + tig4);                          \
            uint32_t b3 = ldv32(hprev16 + 48 + tig4);                          \
            float dN0a[4], dN0b[4], dN1a[4], dN1b[4];                          \
            /* 4 INDEPENDENT n-MMAs: k-halves in separate accumulators */      \
            MMA_LD(dN0a, af[0][0], b0, b1, bn0a, fz, bn0b, fz);                \
            MMA_LD(dN0b, af[0][1], b2, b3, fz, fz, fz, fz);                    \
            MMA_LD(dN1a, af[1][0], b0, b1, bn1a, fz, bn1b, fz);                \
            MMA_LD(dN1b, af[1][1], b2, b3, fz, fz, fz, fz);                    \
            /* full h row (broadcast) for the fma-pipe r,z dots */             \
            uint32_t hu[16];                                                   \
            ldsv128u(hprev16 +  0, hu[0],  hu[1],  hu[2],  hu[3]);             \
            ldsv128u(hprev16 + 16, hu[4],  hu[5],  hu[6],  hu[7]);             \
            ldsv128u(hprev16 + 32, hu[8],  hu[9],  hu[10], hu[11]);            \
            ldsv128u(hprev16 + 48, hu[12], hu[13], hu[14], hu[15]);            \
            __half2 h2[16];                                                    \
            _Pragma("unroll")                                                  \
            for (int j = 0; j < 16; j++) h2[j] = u2h2(hu[j]);                  \
            const __half2 hz2 = __half2half2(__ushort_as_half((unsigned short)0)); \
            /* r-dot: 4 accumulators (critical path) */                        \
            __half2 ar0 = hz2, ar1 = hz2, ar2 = hz2, ar3 = hz2;                \
            _Pragma("unroll")                                                  \
            for (int j = 0; j < 16; j += 4) {                                  \
                ar0 = __hfma2(wr[j],     h2[j],     ar0);                      \
                ar1 = __hfma2(wr[j + 1], h2[j + 1], ar1);                      \
                ar2 = __hfma2(wr[j + 2], h2[j + 2], ar2);                      \
                ar3 = __hfma2(wr[j + 3], h2[j + 3], ar3);                      \
            }                                                                  \
            __half2 sr = __hadd2(__hadd2(ar0, ar1), __hadd2(ar2, ar3));        \
            /* z-dot: 2 accumulators (slack path) */                           \
            __half2 az0 = hz2, az1 = hz2;                                      \
            _Pragma("unroll")                                                  \
            for (int j = 0; j < 16; j += 2) {                                  \
                az0 = __hfma2(wz[j],     h2[j],     az0);                      \
                az1 = __hfma2(wz[j + 1], h2[j + 1], az1);                      \
            }                                                                  \
            __half2 sz = __hadd2(az0, az1);                                    \
            /* packed cross-half reduce for r,z together */                    \
            __half2 pa = __lows2half2(sr, sz);                                 \
            __half2 pb = __highs2half2(sr, sz);                                \
            __half2 srz = __hadd2(pa, pb);          /* {rdot, zdot} */         \
            float2 frz = __half22float2(srz);                                  \
            float tr = tanhm(frz.x + gx.x);                                    \
            float tz = tanhm(frz.y + gx.y);                                    \
            /* n extraction per k-half (SELs hidden under tanh), then merge */ \
            float n0 = pt2 ? (p3 ? dN1a[2] : dN1a[0]) : (p1 ? dN0a[2] : dN0a[0]); \
            float n1 = pt2 ? (p3 ? dN1b[2] : dN1b[0]) : (p1 ? dN0b[2] : dN0b[0]); \
            float ns = n0 + n1;                     /* 0.5*(Wn.h + bhn) */     \
            float nsc = gx.z + ns;                                             \
            float argn = fmaf(tr, ns, nsc);         /* xn + r*hn */            \
            float tn = tanhm(argn);                                            \
            float zz = fmaf(0.5f, tz, 0.5f);                                   \
            float cb = zz * hk;                                                \
            float ca = 1.0f - zz;                                              \
            hk = fmaf(ca, tn, cb);                  /* h_new (f32) */          \
            stv16((H16ROW) + u * 2, __half_as_ushort(__float2half_rn(hk)));    \
            sts32p((HROWF) + u * 4, hk);            /* exact copy for FC */    \
            hprev16 = (H16ROW);                                                \
        }

        for (int c = 0; c < NCH; c++) {
            __syncthreads();
            int nst = L - c * CH;
            nst = nst < 0 ? 0 : (nst > CH ? CH : nst);
            const int cb1 = c & 1;
            uint32_t h16row = h16base + (cb1 * CH * Hq) * 2;
            uint32_t hrowf = hbase + (cb1 * CH * HPAD) * 4;
            if (nst == CH) {
#pragma unroll 4
                for (int s = 0; s < CH; s++) {
                    GRU_STEP(cb1, s, h16row, hrowf)
                    h16row += Hq * 2;
                    hrowf += HPAD * 4;
                }
            } else {
#pragma unroll 1
                for (int s = 0; s < nst; s++) {
                    GRU_STEP(cb1, s, h16row, hrowf)
                    h16row += Hq * 2;
                    hrowf += HPAD * 4;
                }
            }
        }
        __syncthreads();
#undef GRU_STEP
    } else if (warp == 1) {
        // ================= FC output, one chunk behind =================
        for (int c = 0; c < NCH; c++) {
            __syncthreads();
            if (c > 0) {
                const int cp = c - 1;
                const int t = cp * CH + lane;
                float o0 = __ldg(fc_b + 0);
                float o1 = __ldg(fc_b + 1);
                if (t < L) {
                    const float* hr = &s_h[cp & 1][lane][0];
#pragma unroll
                    for (int j = 0; j < Hq; j++) {
                        float hv = hr[j];
                        o0 = fmaf(__ldg(fc_w + j), hv, o0);
                        o1 = fmaf(__ldg(fc_w + Hq + j), hv, o1);
                    }
                }
                float2 v = make_float2(o0, o1);
                *reinterpret_cast<float2*>(out + ((size_t)b * Tq + t) * Oq) = v;
            }
        }
        __syncthreads();
        {   // epilogue: last chunk
            const int cp = NCH - 1;
            const int t = cp * CH + lane;
            float o0 = __ldg(fc_b + 0);
            float o1 = __ldg(fc_b + 1);
            if (t < L) {
                const float* hr = &s_h[cp & 1][lane][0];
#pragma unroll
                for (int j = 0; j < Hq; j++) {
                    float hv = hr[j];
                    o0 = fmaf(__ldg(fc_w + j), hv, o0);
                    o1 = fmaf(__ldg(fc_w + Hq + j), hv, o1);
                }
            }
            float2 v = make_float2(o0, o1);
            *reinterpret_cast<float2*>(out + ((size_t)b * Tq + t) * Oq) = v;
        }
    } else {
        // ================= producers (warps 2,3), one chunk ahead =================
        float wiA[Iq], wiB[Iq], wiC[Iq];
#pragma unroll
        for (int i = 0; i < Iq; i++) {
            wiA[i] = 0.5f * w_ih[lane * Iq + i];          // pre-scaled for tanh-form
            wiB[i] = 0.5f * w_ih[(Hq + lane) * Iq + i];
            wiC[i] = w_ih[(2 * Hq + lane) * Iq + i];      // pn: unscaled
        }
        const float biA = 0.5f * (b_ih[lane] + b_hh[lane]);
        const float biB = 0.5f * (b_ih[Hq + lane] + b_hh[Hq + lane]);
        const float biC = b_ih[2 * Hq + lane];
        const int s0 = (warp == 3) ? (CH / 2) : 0;

        // prologue: chunk 0
        {
            const float* xp = x + ((size_t)b * Tq + s0) * Iq;
#pragma unroll 1
            for (int s = 0; s < CH / 2; s++) {
                float xv[Iq];
#pragma unroll
                for (int i = 0; i < Iq; i++) xv[i] = xp[i];
                float gr = biA, gz = biB, gn = biC;
#pragma unroll
                for (int i = 0; i < Iq; i++) {
                    gr = fmaf(wiA[i], xv[i], gr);
                    gz = fmaf(wiB[i], xv[i], gz);
                    gn = fmaf(wiC[i], xv[i], gn);
                }
                s_gx[0][s0 + s][lane] = make_float4(gr, gz, gn, 0.0f);
                xp += Iq;
            }
        }
        for (int c = 0; c < NCH; c++) {
            __syncthreads();
            const int cc = c + 1;
            if (cc < NCH) {
                const float* xp = x + ((size_t)b * Tq + cc * CH + s0) * Iq;
#pragma unroll 1
                for (int s = 0; s < CH / 2; s++) {
                    float xv[Iq];
#pragma unroll
                    for (int i = 0; i < Iq; i++) xv[i] = xp[i];
                    float gr = biA, gz = biB, gn = biC;
#pragma unroll
                    for (int i = 0; i < Iq; i++) {
                        gr = fmaf(wiA[i], xv[i], gr);
                        gz = fmaf(wiB[i], xv[i], gz);
                        gn = fmaf(wiC[i], xv[i], gn);
                    }
                    s_gx[cc & 1][s0 + s][lane] = make_float4(gr, gz, gn, 0.0f);
                    xp += Iq;
                }
            }
        }
        __syncthreads();
    }
}

extern "C" void kernel_launch(void* const* d_in, const int* in_sizes, int n_in,
                              void* d_out, int out_size) {
    const float* x       = (const float*)d_in[0];
    const int*   lengths = (const int*)d_in[1];
    const float* w_ih    = (const float*)d_in[2];
    const float* w_hh    = (const float*)d_in[3];
    const float* b_ih    = (const float*)d_in[4];
    const float* b_hh    = (const float*)d_in[5];
    const float* fc_w    = (const float*)d_in[6];
    const float* fc_b    = (const float*)d_in[7];
    float* out = (float*)d_out;

    gru_seq_kernel<<<Bq, 128>>>(x, lengths, w_ih, w_hh, b_ih, b_hh, fc_w, fc_b, out);
}

// round 14
// speedup vs baseline: 1.2720x; 1.1390x over previous
#include <cuda_runtime.h>
#include <cuda_fp16.h>
#include <cstdint>

// GRU: B=128, T=4096, I=6, H=32, O=2. One CTA per sequence, 4 warps:
//   warp 0: recurrence via tensor-core GEMV y(96) = W_hh(96x32).h(32):
//           12x mma.m16n8k16 (f16 in, f32 accum), chained k-pairs (R10 form —
//           proven fastest; hybrids/unchaining all regressed, R11-R13).
//           Tail trimmed: late-z algebra h = tn + z*(hk - tn), depth-2 SEL
//           extraction, gx load deferred past MMA issue.
//   warp 1: FC output, one chunk behind (exact f32 h ring)
//   warps 2,3: gx producers, one chunk ahead (f32)
// Unit ownership follows the MMA D-fragment: u = gid + 8*(tig&1) + 16*(tig>>1).

#define Bq 128
#define Tq 4096
#define Iq 6
#define Hq 32
#define Oq 2
#define CH 32
#define NCH (Tq / CH)
#define HPAD 36   // f32 h ring rows: 144B

__device__ __forceinline__ float tanhm(float x) { float y; asm("tanh.approx.f32 %0, %1;" : "=f"(y) : "f"(x)); return y; }

__device__ __forceinline__ uint32_t saddr(const void* p) {
    uint32_t a;
    asm("{ .reg .u64 t; cvta.to.shared.u64 t, %1; cvt.u32.u64 %0, t; }" : "=r"(a) : "l"(p));
    return a;
}
__device__ __forceinline__ uint32_t ldv32(uint32_t a) {
    uint32_t v; asm volatile("ld.volatile.shared.b32 %0, [%1];" : "=r"(v) : "r"(a)); return v;
}
__device__ __forceinline__ void stv16(uint32_t a, unsigned short v) {
    asm volatile("st.volatile.shared.u16 [%0], %1;" :: "r"(a), "h"(v));
}
__device__ __forceinline__ void sts32p(uint32_t a, float v) {
    asm volatile("st.shared.f32 [%0], %1;" :: "r"(a), "f"(v));
}
__device__ __forceinline__ uint32_t packh2(float lo, float hi) {
    __half2 h = __floats2half2_rn(lo, hi);
    return *(uint32_t*)&h;
}

// D (fresh) = A*B + Cq
#define MMA_LD(D, A, B0, B1, C0, C1, C2, C3)                                   \
    asm volatile(                                                              \
        "mma.sync.aligned.m16n8k16.row.col.f32.f16.f16.f32 "                   \
        "{%0,%1,%2,%3}, {%4,%5,%6,%7}, {%8,%9}, {%10,%11,%12,%13};"            \
        : "=f"((D)[0]), "=f"((D)[1]), "=f"((D)[2]), "=f"((D)[3])               \
        : "r"((A)[0]), "r"((A)[1]), "r"((A)[2]), "r"((A)[3]),                  \
          "r"(B0), "r"(B1),                                                    \
          "f"(C0), "f"(C1), "f"(C2), "f"(C3))

// D += A*B (in place)
#define MMA_ACC(D, A, B0, B1)                                                  \
    asm volatile(                                                              \
        "mma.sync.aligned.m16n8k16.row.col.f32.f16.f16.f32 "                   \
        "{%0,%1,%2,%3}, {%4,%5,%6,%7}, {%8,%9}, {%0,%1,%2,%3};"                \
        : "+f"((D)[0]), "+f"((D)[1]), "+f"((D)[2]), "+f"((D)[3])               \
        : "r"((A)[0]), "r"((A)[1]), "r"((A)[2]), "r"((A)[3]),                  \
          "r"(B0), "r"(B1))

__global__ void __launch_bounds__(128, 1) gru_seq_kernel(
    const float* __restrict__ x,        // [B, T, I]
    const int*   __restrict__ lengths,  // [B]
    const float* __restrict__ w_ih,     // [3H, I]
    const float* __restrict__ w_hh,     // [3H, H]  (96 x 32 row-major)
    const float* __restrict__ b_ih,     // [3H]
    const float* __restrict__ b_hh,     // [3H]
    const float* __restrict__ fc_w,     // [O, H]
    const float* __restrict__ fc_b,     // [O]
    float* __restrict__ out)            // [B, T, O]
{
    __shared__ __align__(16) float4 s_gx[2][CH][Hq];   // {pr, pz, pn, 0} by hidden unit
    __shared__ __align__(16) float  s_h[2][CH][HPAD];  // f32 h ring (for FC)
    __shared__ __align__(16) __half s_h16[2][CH][Hq];  // f16 h ring (64B rows)

    const int lane = threadIdx.x & 31;
    const int warp = threadIdx.x >> 5;
    const int b = blockIdx.x;
    const int L = lengths[b];

    const uint32_t hbase   = saddr(&s_h[0][0][0]);
    const uint32_t h16base = saddr(&s_h16[0][0][0]);

    if (warp == 0) {
        // ================= recurrence (tensor-core GEMV) =================
        const int gid = lane >> 2;          // groupID (0..7)
        const int tig = lane & 3;           // thread-in-group
        const int u = gid + ((tig & 1) << 3) + ((tig & 2) << 3);  // owned hidden unit
        const bool p1 = (tig == 1), p3 = (tig == 3);
        const bool pt2 = (tig & 2) != 0;

        // A fragments: af[mt][kt][4]; m0,m1 = r rows; m2,m3 = z; m4,m5 = n.
        uint32_t af[6][2][4];
#pragma unroll
        for (int mt = 0; mt < 6; mt++)
#pragma unroll
            for (int kt = 0; kt < 2; kt++) {
                const int r0 = mt * 16 + gid;
                const int r1 = r0 + 8;
                const int c0 = kt * 16 + 2 * tig;
                af[mt][kt][0] = packh2(0.5f * w_hh[r0 * Hq + c0],     0.5f * w_hh[r0 * Hq + c0 + 1]);
                af[mt][kt][1] = packh2(0.5f * w_hh[r1 * Hq + c0],     0.5f * w_hh[r1 * Hq + c0 + 1]);
                af[mt][kt][2] = packh2(0.5f * w_hh[r0 * Hq + c0 + 8], 0.5f * w_hh[r0 * Hq + c0 + 9]);
                af[mt][kt][3] = packh2(0.5f * w_hh[r1 * Hq + c0 + 8], 0.5f * w_hh[r1 * Hq + c0 + 9]);
            }
        // n-tile bias C-quads (0.5*bhn by row), r/z use zero quad
        const float bn4a = 0.5f * b_hh[2 * Hq + gid];
        const float bn4b = 0.5f * b_hh[2 * Hq + gid + 8];
        const float bn5a = 0.5f * b_hh[2 * Hq + 16 + gid];
        const float bn5b = 0.5f * b_hh[2 * Hq + 24 + gid];
        const float fz = 0.0f;

        stv16(h16base + ((1 * CH + (CH - 1)) * Hq + u) * 2, (unsigned short)0);  // h_{-1}=0
        float hk = 0.f;
        uint32_t hprev16 = h16base + ((1 * CH + (CH - 1)) * Hq) * 2;
        const uint32_t tig4 = tig * 4;

#define GRU_STEP(CBUF, S, H16ROW, HROWF)                                       \
        {                                                                      \
            /* B fragments FIRST — nothing delays MMA issue */                 \
            uint32_t b0 = ldv32(hprev16 + tig4);                               \
            uint32_t b1 = ldv32(hprev16 + 16 + tig4);                          \
            uint32_t b2 = ldv32(hprev16 + 32 + tig4);                          \
            uint32_t b3 = ldv32(hprev16 + 48 + tig4);                          \
            float dR0[4], dR1[4], dZ0[4], dZ1[4], dN0[4], dN1[4];              \
            /* r first (critical), then n, z last (late-z algebra) */          \
            MMA_LD(dR0, af[0][0], b0, b1, fz, fz, fz, fz);                     \
            MMA_ACC(dR0, af[0][1], b2, b3);                                    \
            MMA_LD(dR1, af[1][0], b0, b1, fz, fz, fz, fz);                     \
            MMA_ACC(dR1, af[1][1], b2, b3);                                    \
            MMA_LD(dN0, af[4][0], b0, b1, bn4a, fz, bn4b, fz);                 \
            MMA_ACC(dN0, af[4][1], b2, b3);                                    \
            MMA_LD(dN1, af[5][0], b0, b1, bn5a, fz, bn5b, fz);                 \
            MMA_ACC(dN1, af[5][1], b2, b3);                                    \
            MMA_LD(dZ0, af[2][0], b0, b1, fz, fz, fz, fz);                     \
            MMA_ACC(dZ0, af[2][1], b2, b3);                                    \
            MMA_LD(dZ1, af[3][0], b0, b1, fz, fz, fz, fz);                     \
            MMA_ACC(dZ1, af[3][1], b2, b3);                                    \
            /* gx load AFTER MMA issue — first needed at tr */                 \
            float4 gx = s_gx[CBUF][S][u];                                      \
            /* depth-2 select trees (balanced, off the serial SEL chain) */    \
            float rdot = pt2 ? (p3 ? dR1[2] : dR1[0]) : (p1 ? dR0[2] : dR0[0]); \
            float tr = tanhm(rdot + gx.x);                                     \
            float ns = pt2 ? (p3 ? dN1[2] : dN1[0]) : (p1 ? dN0[2] : dN0[0]);  \
            float nsc = gx.z + ns;                                             \
            float argn = fmaf(tr, ns, nsc);         /* xn + r*hn */            \
            float tn = tanhm(argn);                                            \
            float d = hk - tn;                      /* pre-z: h = tn + z*d */  \
            float zdot = pt2 ? (p3 ? dZ1[2] : dZ1[0]) : (p1 ? dZ0[2] : dZ0[0]); \
            float tz = tanhm(zdot + gx.y);                                     \
            float zz = fmaf(0.5f, tz, 0.5f);                                   \
            hk = fmaf(zz, d, tn);                   /* h_new (f32) */          \
            stv16((H16ROW) + u * 2, __half_as_ushort(__float2half_rn(hk)));    \
            sts32p((HROWF) + u * 4, hk);            /* exact copy for FC */    \
            hprev16 = (H16ROW);                                                \
        }

        for (int c = 0; c < NCH; c++) {
            __syncthreads();
            int nst = L - c * CH;
            nst = nst < 0 ? 0 : (nst > CH ? CH : nst);
            const int cb1 = c & 1;
            uint32_t h16row = h16base + (cb1 * CH * Hq) * 2;
            uint32_t hrowf = hbase + (cb1 * CH * HPAD) * 4;
            if (nst == CH) {
#pragma unroll 4
                for (int s = 0; s < CH; s++) {
                    GRU_STEP(cb1, s, h16row, hrowf)
                    h16row += Hq * 2;
                    hrowf += HPAD * 4;
                }
            } else {
#pragma unroll 1
                for (int s = 0; s < nst; s++) {
                    GRU_STEP(cb1, s, h16row, hrowf)
                    h16row += Hq * 2;
                    hrowf += HPAD * 4;
                }
            }
        }
        __syncthreads();
#undef GRU_STEP
    } else if (warp == 1) {
        // ================= FC output, one chunk behind =================
        for (int c = 0; c < NCH; c++) {
            __syncthreads();
            if (c > 0) {
                const int cp = c - 1;
                const int t = cp * CH + lane;
                float o0 = __ldg(fc_b + 0);
                float o1 = __ldg(fc_b + 1);
                if (t < L) {
                    const float* hr = &s_h[cp & 1][lane][0];
#pragma unroll
                    for (int j = 0; j < Hq; j++) {
                        float hv = hr[j];
                        o0 = fmaf(__ldg(fc_w + j), hv, o0);
                        o1 = fmaf(__ldg(fc_w + Hq + j), hv, o1);
                    }
                }
                float2 v = make_float2(o0, o1);
                *reinterpret_cast<float2*>(out + ((size_t)b * Tq + t) * Oq) = v;
            }
        }
        __syncthreads();
        {   // epilogue: last chunk
            const int cp = NCH - 1;
            const int t = cp * CH + lane;
            float o0 = __ldg(fc_b + 0);
            float o1 = __ldg(fc_b + 1);
            if (t < L) {
                const float* hr = &s_h[cp & 1][lane][0];
#pragma unroll
                for (int j = 0; j < Hq; j++) {
                    float hv = hr[j];
                    o0 = fmaf(__ldg(fc_w + j), hv, o0);
                    o1 = fmaf(__ldg(fc_w + Hq + j), hv, o1);
                }
            }
            float2 v = make_float2(o0, o1);
            *reinterpret_cast<float2*>(out + ((size_t)b * Tq + t) * Oq) = v;
        }
    } else {
        // ================= producers (warps 2,3), one chunk ahead =================
        float wiA[Iq], wiB[Iq], wiC[Iq];
#pragma unroll
        for (int i = 0; i < Iq; i++) {
            wiA[i] = 0.5f * w_ih[lane * Iq + i];          // pre-scaled for tanh-form
            wiB[i] = 0.5f * w_ih[(Hq + lane) * Iq + i];
            wiC[i] = w_ih[(2 * Hq + lane) * Iq + i];      // pn: unscaled
        }
        const float biA = 0.5f * (b_ih[lane] + b_hh[lane]);
        const float biB = 0.5f * (b_ih[Hq + lane] + b_hh[Hq + lane]);
        const float biC = b_ih[2 * Hq + lane];
        const int s0 = (warp == 3) ? (CH / 2) : 0;

        // prologue: chunk 0
        {
            const float* xp = x + ((size_t)b * Tq + s0) * Iq;
#pragma unroll 1
            for (int s = 0; s < CH / 2; s++) {
                float xv[Iq];
#pragma unroll
                for (int i = 0; i < Iq; i++) xv[i] = xp[i];
                float gr = biA, gz = biB, gn = biC;
#pragma unroll
                for (int i = 0; i < Iq; i++) {
                    gr = fmaf(wiA[i], xv[i], gr);
                    gz = fmaf(wiB[i], xv[i], gz);
                    gn = fmaf(wiC[i], xv[i], gn);
                }
                s_gx[0][s0 + s][lane] = make_float4(gr, gz, gn, 0.0f);
                xp += Iq;
            }
        }
        for (int c = 0; c < NCH; c++) {
            __syncthreads();
            const int cc = c + 1;
            if (cc < NCH) {
                const float* xp = x + ((size_t)b * Tq + cc * CH + s0) * Iq;
#pragma unroll 1
                for (int s = 0; s < CH / 2; s++) {
                    float xv[Iq];
#pragma unroll
                    for (int i = 0; i < Iq; i++) xv[i] = xp[i];
                    float gr = biA, gz = biB, gn = biC;
#pragma unroll
                    for (int i = 0; i < Iq; i++) {
                        gr = fmaf(wiA[i], xv[i], gr);
                        gz = fmaf(wiB[i], xv[i], gz);
                        gn = fmaf(wiC[i], xv[i], gn);
                    }
                    s_gx[cc & 1][s0 + s][lane] = make_float4(gr, gz, gn, 0.0f);
                    xp += Iq;
                }
            }
        }
        __syncthreads();
    }
}

extern "C" void kernel_launch(void* const* d_in, const int* in_sizes, int n_in,
                              void* d_out, int out_size) {
    const float* x       = (const float*)d_in[0];
    const int*   lengths = (const int*)d_in[1];
    const float* w_ih    = (const float*)d_in[2];
    const float* w_hh    = (const float*)d_in[3];
    const float* b_ih    = (const float*)d_in[4];
    const float* b_hh    = (const float*)d_in[5];
    const float* fc_w    = (const float*)d_in[6];
    const float* fc_b    = (const float*)d_in[7];
    float* out = (float*)d_out;

    gru_seq_kernel<<<Bq, 128>>>(x, lengths, w_ih, w_hh, b_ih, b_hh, fc_w, fc_b, out);
}

// round 16
// speedup vs baseline: 1.2906x; 1.0146x over previous
#include <cuda_runtime.h>
#include <cuda_fp16.h>
#include <cstdint>

// GRU: B=128, T=4096, I=6, H=32, O=2. One CTA per sequence, 4 warps:
//   warp 0: recurrence, MIXED-precision tensor GEMV (8 MMAs vs 12 in R14):
//           r,z gates: 4x mma.m16n8k32.s8 (full K per MMA; layout validated
//             by R15's quant-level-only error), per-row scales.
//           n gate: 4x independent mma.m16n8k16.f16 (R10-validated layout,
//             f32 accumulate) — n feeds h directly, so it must stay f16:
//             R15 showed all-int8 n costs 1.1e-3 total error.
//           h kept in THREE forms: f32 (FC, exact), f16 (n dots), s8 (r/z).
//   warp 1: FC output, one chunk behind (exact f32 h ring)
//   warps 2,3: gx producers, one chunk ahead (f32)
// Unit ownership follows the MMA D-fragment: u = gid + 8*(tig&1) + 16*(tig>>1).
// Gate algebra: tr = tanh(idotR*fr + pr); tz analogous (0.5 folded in consts);
//   ns = 0.5*(Wn.h + bhn) via f16 MMA (0.5 pre-scaled weights, bias in C);
//   argn = pn + ns + tr*ns ; h = tn + z*(h-tn) via folded fma.

#define Bq 128
#define Tq 4096
#define Iq 6
#define Hq 32
#define Oq 2
#define CH 32
#define NCH (Tq / CH)
#define HPAD 36   // f32 h ring rows: 144B

__device__ __forceinline__ float tanhm(float x) { float y; asm("tanh.approx.f32 %0, %1;" : "=f"(y) : "f"(x)); return y; }

__device__ __forceinline__ uint32_t saddr(const void* p) {
    uint32_t a;
    asm("{ .reg .u64 t; cvta.to.shared.u64 t, %1; cvt.u32.u64 %0, t; }" : "=r"(a) : "l"(p));
    return a;
}
__device__ __forceinline__ uint32_t ldv32(uint32_t a) {
    uint32_t v; asm volatile("ld.volatile.shared.b32 %0, [%1];" : "=r"(v) : "r"(a)); return v;
}
__device__ __forceinline__ void stv16(uint32_t a, unsigned short v) {
    asm volatile("st.volatile.shared.u16 [%0], %1;" :: "r"(a), "h"(v));
}
__device__ __forceinline__ void stv8(uint32_t a, uint32_t v) {
    asm volatile("st.volatile.shared.u8 [%0], %1;" :: "r"(a), "r"(v));
}
__device__ __forceinline__ void sts32p(uint32_t a, float v) {
    asm volatile("st.shared.f32 [%0], %1;" :: "r"(a), "f"(v));
}
__device__ __forceinline__ uint32_t packh2(float lo, float hi) {
    __half2 h = __floats2half2_rn(lo, hi);
    return *(uint32_t*)&h;
}

// f16: D (f32, fresh) = A*B + Cq
#define MMA_LD(D, A, B0, B1, C0, C1, C2, C3)                                   \
    asm volatile(                                                              \
        "mma.sync.aligned.m16n8k16.row.col.f32.f16.f16.f32 "                   \
        "{%0,%1,%2,%3}, {%4,%5,%6,%7}, {%8,%9}, {%10,%11,%12,%13};"            \
        : "=f"((D)[0]), "=f"((D)[1]), "=f"((D)[2]), "=f"((D)[3])               \
        : "r"((A)[0]), "r"((A)[1]), "r"((A)[2]), "r"((A)[3]),                  \
          "r"(B0), "r"(B1),                                                    \
          "f"(C0), "f"(C1), "f"(C2), "f"(C3))

// int8: D (s32, fresh) = A*B
#define MMAI(D, A, B0, B1)                                                     \
    asm volatile(                                                              \
        "mma.sync.aligned.m16n8k32.row.col.s32.s8.s8.s32 "                     \
        "{%0,%1,%2,%3}, {%4,%5,%6,%7}, {%8,%9}, {%10,%11,%12,%13};"            \
        : "=r"((D)[0]), "=r"((D)[1]), "=r"((D)[2]), "=r"((D)[3])               \
        : "r"((A)[0]), "r"((A)[1]), "r"((A)[2]), "r"((A)[3]),                  \
          "r"(B0), "r"(B1),                                                    \
          "r"(0), "r"(0), "r"(0), "r"(0))

__global__ void __launch_bounds__(128, 1) gru_seq_kernel(
    const float* __restrict__ x,        // [B, T, I]
    const int*   __restrict__ lengths,  // [B]
    const float* __restrict__ w_ih,     // [3H, I]
    const float* __restrict__ w_hh,     // [3H, H]  (96 x 32 row-major)
    const float* __restrict__ b_ih,     // [3H]
    const float* __restrict__ b_hh,     // [3H]
    const float* __restrict__ fc_w,     // [O, H]
    const float* __restrict__ fc_b,     // [O]
    float* __restrict__ out)            // [B, T, O]
{
    __shared__ __align__(16) float4  s_gx[2][CH][Hq];   // {pr, pz, pn, 0} by hidden unit
    __shared__ __align__(16) float   s_h[2][CH][HPAD];  // f32 h ring (for FC)
    __shared__ __align__(16) __half  s_h16[2][CH][Hq];  // f16 h ring (n dots)
    __shared__ __align__(4)  uint8_t s_h8[2][CH][Hq];   // s8 h ring (r/z dots)
    __shared__ float s_scale[2 * Hq];                   // per-row |w|max (r,z rows)

    const int lane = threadIdx.x & 31;
    const int warp = threadIdx.x >> 5;
    const int b = blockIdx.x;
    const int L = lengths[b];

    const uint32_t hbase   = saddr(&s_h[0][0][0]);
    const uint32_t h16base = saddr(&s_h16[0][0][0]);
    const uint32_t h8base  = saddr(&s_h8[0][0][0]);

    if (warp == 0) {
        // ================= recurrence (mixed int8/f16 tensor GEMV) =========
        const int gid = lane >> 2;          // groupID (0..7)
        const int tig = lane & 3;           // thread-in-group
        const int u = gid + ((tig & 1) << 3) + ((tig & 2) << 3);  // owned hidden unit
        const bool p1 = (tig == 1), p3 = (tig == 3);
        const bool pt2 = (tig & 2) != 0;

        // --- per-row weight scales for r,z rows (setup) ---
        for (int r = lane; r < 2 * Hq; r += 32) {
            float m = 0.0f;
            const float* wr = w_hh + r * Hq;
#pragma unroll
            for (int k = 0; k < Hq; k++) m = fmaxf(m, fabsf(wr[k]));
            s_scale[r] = (m > 0.0f) ? m : 1.0f;
        }
        __syncwarp();

        // --- int8 A fragments: tiles 0,1 = r rows; 2,3 = z rows ---
        // reg layout {row0 klo, row1 klo, row0 khi, row1 khi}; klo=4tig.., khi=16+4tig..
        uint32_t afi[4][4];
#pragma unroll
        for (int t = 0; t < 4; t++) {
            const int r0 = t * 16 + gid;
            const int r1 = r0 + 8;
            const float is0 = 127.0f / s_scale[r0];
            const float is1 = 127.0f / s_scale[r1];
            const int klo = 4 * tig, khi = 16 + 4 * tig;
            uint32_t v0 = 0, v1 = 0, v2 = 0, v3 = 0;
#pragma unroll
            for (int j = 0; j < 4; j++) {
                int q0 = __float2int_rn(w_hh[r0 * Hq + klo + j] * is0);
                int q1 = __float2int_rn(w_hh[r1 * Hq + klo + j] * is1);
                int q2 = __float2int_rn(w_hh[r0 * Hq + khi + j] * is0);
                int q3 = __float2int_rn(w_hh[r1 * Hq + khi + j] * is1);
                v0 |= (uint32_t)(q0 & 0xFF) << (8 * j);
                v1 |= (uint32_t)(q1 & 0xFF) << (8 * j);
                v2 |= (uint32_t)(q2 & 0xFF) << (8 * j);
                v3 |= (uint32_t)(q3 & 0xFF) << (8 * j);
            }
            afi[t][0] = v0; afi[t][1] = v1; afi[t][2] = v2; afi[t][3] = v3;
        }
        // --- f16 A fragments for n: 2 m-tiles x 2 k-halves, 0.5-scaled ---
        uint32_t afn[2][2][4];
#pragma unroll
        for (int mt = 0; mt < 2; mt++)
#pragma unroll
            for (int kt = 0; kt < 2; kt++) {
                const int r0 = 2 * Hq + mt * 16 + gid;
                const int r1 = r0 + 8;
                const int c0 = kt * 16 + 2 * tig;
                afn[mt][kt][0] = packh2(0.5f * w_hh[r0 * Hq + c0],     0.5f * w_hh[r0 * Hq + c0 + 1]);
                afn[mt][kt][1] = packh2(0.5f * w_hh[r1 * Hq + c0],     0.5f * w_hh[r1 * Hq + c0 + 1]);
                afn[mt][kt][2] = packh2(0.5f * w_hh[r0 * Hq + c0 + 8], 0.5f * w_hh[r0 * Hq + c0 + 9]);
                afn[mt][kt][3] = packh2(0.5f * w_hh[r1 * Hq + c0 + 8], 0.5f * w_hh[r1 * Hq + c0 + 9]);
            }
        // n-tile bias C-quads (0.5*bhn by row) on the k0 MMA
        const float bn0a = 0.5f * b_hh[2 * Hq + gid];
        const float bn0b = 0.5f * b_hh[2 * Hq + gid + 8];
        const float bn1a = 0.5f * b_hh[2 * Hq + 16 + gid];
        const float bn1b = 0.5f * b_hh[2 * Hq + 24 + gid];
        const float fzr = 0.0f;
        // per-lane dequant constants for r,z (0.5 gate-fold + h scale 1/127)
        const float DQ = 0.5f / (127.0f * 127.0f);
        const float fr  = DQ * s_scale[u];
        const float fzc = DQ * s_scale[Hq + u];

        // h_{-1} = 0 rows (f16 + s8)
        stv16(h16base + ((1 * CH + (CH - 1)) * Hq + u) * 2, (unsigned short)0);
        stv8(h8base + ((1 * CH + (CH - 1)) * Hq + u), 0u);
        float hk = 0.f;
        uint32_t hprev16 = h16base + ((1 * CH + (CH - 1)) * Hq) * 2;
        uint32_t hprev8  = h8base + ((1 * CH + (CH - 1)) * Hq);
        const uint32_t tig4 = tig * 4;

#define GRU_STEP(CBUF, S, H16ROW, H8ROW, HROWF)                                \
        {                                                                      \
            /* int8 B fragments (r/z) first — r is the critical gate */        \
            uint32_t c0 = ldv32(hprev8 + tig4);                                \
            uint32_t c1 = ldv32(hprev8 + 16 + tig4);                           \
            int dR0[4], dR1[4], dZ0[4], dZ1[4];                                \
            MMAI(dR0, afi[0], c0, c1);                                         \
            MMAI(dR1, afi[1], c0, c1);                                         \
            /* f16 B fragments (n) */                                          \
            uint32_t b0 = ldv32(hprev16 + tig4);                               \
            uint32_t b1 = ldv32(hprev16 + 16 + tig4);                          \
            uint32_t b2 = ldv32(hprev16 + 32 + tig4);                          \
            uint32_t b3 = ldv32(hprev16 + 48 + tig4);                          \
            float dN0a[4], dN0b[4], dN1a[4], dN1b[4];                          \
            MMA_LD(dN0a, afn[0][0], b0, b1, bn0a, fzr, bn0b, fzr);             \
            MMA_LD(dN0b, afn[0][1], b2, b3, fzr, fzr, fzr, fzr);               \
            MMA_LD(dN1a, afn[1][0], b0, b1, bn1a, fzr, bn1b, fzr);             \
            MMA_LD(dN1b, afn[1][1], b2, b3, fzr, fzr, fzr, fzr);               \
            MMAI(dZ0, afi[2], c0, c1);                                         \
            MMAI(dZ1, afi[3], c0, c1);                                         \
            float4 gx = s_gx[CBUF][S][u];                                      \
            int iR = pt2 ? (p3 ? dR1[2] : dR1[0]) : (p1 ? dR0[2] : dR0[0]);    \
            float tr = tanhm(fmaf((float)iR, fr, gx.x));                       \
            float n0 = pt2 ? (p3 ? dN1a[2] : dN1a[0]) : (p1 ? dN0a[2] : dN0a[0]); \
            float n1 = pt2 ? (p3 ? dN1b[2] : dN1b[0]) : (p1 ? dN0b[2] : dN0b[0]); \
            float ns = n0 + n1;                      /* 0.5*(Wn.h + bhn) */    \
            float nsc = gx.z + ns;                                             \
            float argn = fmaf(tr, ns, nsc);          /* xn + r*hn */           \
            float tn = tanhm(argn);                                            \
            float halfd = fmaf(0.5f, hk, -0.5f * tn);                          \
            float tph = tn + halfd;                  /* prepped in z shadow */ \
            int iZ = pt2 ? (p3 ? dZ1[2] : dZ1[0]) : (p1 ? dZ0[2] : dZ0[0]);    \
            float tz = tanhm(fmaf((float)iZ, fzc, gx.y));                      \
            hk = fmaf(halfd, tz, tph);               /* h_new (f32) */         \
            stv16((H16ROW) + u * 2, __half_as_ushort(__float2half_rn(hk)));    \
            int hq = __float2int_rn(hk * 127.0f);                              \
            stv8((H8ROW) + u, (uint32_t)hq);                                   \
            sts32p((HROWF) + u * 4, hk);             /* exact copy for FC */   \
            hprev16 = (H16ROW);                                                \
            hprev8 = (H8ROW);                                                  \
        }

        for (int c = 0; c < NCH; c++) {
            __syncthreads();
            int nst = L - c * CH;
            nst = nst < 0 ? 0 : (nst > CH ? CH : nst);
            const int cb1 = c & 1;
            uint32_t h16row = h16base + (cb1 * CH * Hq) * 2;
            uint32_t h8row  = h8base + (cb1 * CH * Hq);
            uint32_t hrowf  = hbase + (cb1 * CH * HPAD) * 4;
            if (nst == CH) {
#pragma unroll 4
                for (int s = 0; s < CH; s++) {
                    GRU_STEP(cb1, s, h16row, h8row, hrowf)
                    h16row += Hq * 2;
                    h8row += Hq;
                    hrowf += HPAD * 4;
                }
            } else {
#pragma unroll 1
                for (int s = 0; s < nst; s++) {
                    GRU_STEP(cb1, s, h16row, h8row, hrowf)
                    h16row += Hq * 2;
                    h8row += Hq;
                    hrowf += HPAD * 4;
                }
            }
        }
        __syncthreads();
#undef GRU_STEP
    } else if (warp == 1) {
        // ================= FC output, one chunk behind =================
        for (int c = 0; c < NCH; c++) {
            __syncthreads();
            if (c > 0) {
                const int cp = c - 1;
                const int t = cp * CH + lane;
                float o0 = __ldg(fc_b + 0);
                float o1 = __ldg(fc_b + 1);
                if (t < L) {
                    const float* hr = &s_h[cp & 1][lane][0];
#pragma unroll
                    for (int j = 0; j < Hq; j++) {
                        float hv = hr[j];
                        o0 = fmaf(__ldg(fc_w + j), hv, o0);
                        o1 = fmaf(__ldg(fc_w + Hq + j), hv, o1);
                    }
                }
                float2 v = make_float2(o0, o1);
                *reinterpret_cast<float2*>(out + ((size_t)b * Tq + t) * Oq) = v;
            }
        }
        __syncthreads();
        {   // epilogue: last chunk
            const int cp = NCH - 1;
            const int t = cp * CH + lane;
            float o0 = __ldg(fc_b + 0);
            float o1 = __ldg(fc_b + 1);
            if (t < L) {
                const float* hr = &s_h[cp & 1][lane][0];
#pragma unroll
                for (int j = 0; j < Hq; j++) {
                    float hv = hr[j];
                    o0 = fmaf(__ldg(fc_w + j), hv, o0);
                    o1 = fmaf(__ldg(fc_w + Hq + j), hv, o1);
                }
            }
            float2 v = make_float2(o0, o1);
            *reinterpret_cast<float2*>(out + ((size_t)b * Tq + t) * Oq) = v;
        }
    } else {
        // ================= producers (warps 2,3), one chunk ahead =================
        float wiA[Iq], wiB[Iq], wiC[Iq];
#pragma unroll
        for (int i = 0; i < Iq; i++) {
            wiA[i] = 0.5f * w_ih[lane * Iq + i];          // pre-scaled for tanh-form
            wiB[i] = 0.5f * w_ih[(Hq + lane) * Iq + i];
            wiC[i] = w_ih[(2 * Hq + lane) * Iq + i];      // pn: unscaled
        }
        const float biA = 0.5f * (b_ih[lane] + b_hh[lane]);
        const float biB = 0.5f * (b_ih[Hq + lane] + b_hh[Hq + lane]);
        const float biC = b_ih[2 * Hq + lane];
        const int s0 = (warp == 3) ? (CH / 2) : 0;

        // prologue: chunk 0
        {
            const float* xp = x + ((size_t)b * Tq + s0) * Iq;
#pragma unroll 1
            for (int s = 0; s < CH / 2; s++) {
                float xv[Iq];
#pragma unroll
                for (int i = 0; i < Iq; i++) xv[i] = xp[i];
                float gr = biA, gz = biB, gn = biC;
#pragma unroll
                for (int i = 0; i < Iq; i++) {
                    gr = fmaf(wiA[i], xv[i], gr);
                    gz = fmaf(wiB[i], xv[i], gz);
                    gn = fmaf(wiC[i], xv[i], gn);
                }
                s_gx[0][s0 + s][lane] = make_float4(gr, gz, gn, 0.0f);
                xp += Iq;
            }
        }
        for (int c = 0; c < NCH; c++) {
            __syncthreads();
            const int cc = c + 1;
            if (cc < NCH) {
                const float* xp = x + ((size_t)b * Tq + cc * CH + s0) * Iq;
#pragma unroll 1
                for (int s = 0; s < CH / 2; s++) {
                    float xv[Iq];
#pragma unroll
                    for (int i = 0; i < Iq; i++) xv[i] = xp[i];
                    float gr = biA, gz = biB, gn = biC;
#pragma unroll
                    for (int i = 0; i < Iq; i++) {
                        gr = fmaf(wiA[i], xv[i], gr);
                        gz = fmaf(wiB[i], xv[i], gz);
                        gn = fmaf(wiC[i], xv[i], gn);
                    }
                    s_gx[cc & 1][s0 + s][lane] = make_float4(gr, gz, gn, 0.0f);
                    xp += Iq;
                }
            }
        }
        __syncthreads();
    }
}

extern "C" void kernel_launch(void* const* d_in, const int* in_sizes, int n_in,
                              void* d_out, int out_size) {
    const float* x       = (const float*)d_in[0];
    const int*   lengths = (const int*)d_in[1];
    const float* w_ih    = (const float*)d_in[2];
    const float* w_hh    = (const float*)d_in[3];
    const float* b_ih    = (const float*)d_in[4];
    const float* b_hh    = (const float*)d_in[5];
    const float* fc_w    = (const float*)d_in[6];
    const float* fc_b    = (const float*)d_in[7];
    float* out = (float*)d_out;

    gru_seq_kernel<<<Bq, 128>>>(x, lengths, w_ih, w_hh, b_ih, b_hh, fc_w, fc_b, out);
}